// round 7
// baseline (speedup 1.0000x reference)
#include <cuda_runtime.h>
#include <cuda_bf16.h>

// Involution: B=4, C=256, G=16, K=7, S=1, P=3, H=W=56
#define HW 3136
#define XCH 624    // xt per-channel stride: 624 % 32 == 16 -> cq shifts {0,8,0,8} bankpairs
#define WSTR 66    // padded span_w row stride
#define KSTR 228   // kern row stride

__device__ float g_h[4 * 64 * HW];   // h = reduce(x): (4,64,3136) fp32

// ---- f32x2 helpers ----
union F2 { float2 f; unsigned long long u; };
union F4 { float4 f; unsigned long long u[2]; };
__device__ __forceinline__ unsigned long long pk2f(float lo, float hi) {
    unsigned long long d;
    asm("mov.b64 %0, {%1, %2};" : "=l"(d) : "f"(lo), "f"(hi));
    return d;
}
__device__ __forceinline__ void unpk2(unsigned long long v, float& lo, float& hi) {
    asm("mov.b64 {%0, %1}, %2;" : "=f"(lo), "=f"(hi) : "l"(v));
}
__device__ __forceinline__ unsigned long long ffma2(
    unsigned long long a, unsigned long long b, unsigned long long c) {
    unsigned long long d;
    asm("fma.rn.f32x2 %0, %1, %2, %3;" : "=l"(d) : "l"(a), "l"(b), "l"(c));
    return d;
}
__device__ __forceinline__ unsigned long long add2(
    unsigned long long a, unsigned long long b) {
    unsigned long long d;
    asm("add.rn.f32x2 %0, %1, %2;" : "=l"(d) : "l"(a), "l"(b));
    return d;
}

// ---------------------------------------------------------------------------
// Kernel 1: h[b,o,p] = sum_c x[b,c,p]*rw[o,c] + rb[o]
// grid (56,4) = 224 CTAs (1.5 waves), block 256 (224 active).
// Tile: 4 o x 4 px (2 stride-28 pairs), k-paired, FFMA2.
// ---------------------------------------------------------------------------
__global__ __launch_bounds__(256) void reduce_kernel(
    const float* __restrict__ x,
    const float* __restrict__ rw,
    const float* __restrict__ rb)
{
    const int b  = blockIdx.y;
    const int n0 = blockIdx.x * 56;
    __shared__ float ws[64 * 32];
    __shared__ float xs[32 * 56];

    const int tid = threadIdx.x;
    const int og = tid / 14;
    const int pg = tid % 14;
    const int o0 = og * 4;
    const bool act = (tid < 224);

    unsigned long long acc[4][2];
    #pragma unroll
    for (int i = 0; i < 4; i++)
        #pragma unroll
        for (int m = 0; m < 2; m++) acc[i][m] = 0ull;

    for (int kb = 0; kb < 256; kb += 32) {
        #pragma unroll
        for (int i = 0; i < 8; i++) {
            int e = tid + i * 256;
            ws[e] = rw[(e >> 5) * 256 + kb + (e & 31)];
        }
        #pragma unroll
        for (int i = 0; i < 7; i++) {
            int e = tid + i * 256;
            int k = e / 56, p = e - k * 56;
            xs[e] = x[(b * 256 + kb + k) * HW + n0 + p];
        }
        __syncthreads();

        if (act) {
            #pragma unroll 4
            for (int k2 = 0; k2 < 16; k2++) {
                unsigned long long w2[4], h0[2], h1[2];
                #pragma unroll
                for (int i = 0; i < 4; i++) {
                    F2 t; t.f = *(const float2*)&ws[(o0 + i) * 32 + 2 * k2];
                    w2[i] = t.u;
                }
                #pragma unroll
                for (int m = 0; m < 2; m++) {
                    F2 t; t.f = *(const float2*)&xs[(2 * k2) * 56 + 2 * pg + 28 * m];
                    h0[m] = t.u;
                }
                #pragma unroll
                for (int m = 0; m < 2; m++) {
                    F2 t; t.f = *(const float2*)&xs[(2 * k2 + 1) * 56 + 2 * pg + 28 * m];
                    h1[m] = t.u;
                }
                #pragma unroll
                for (int i = 0; i < 4; i++) {
                    float wl, wh;
                    unpk2(w2[i], wl, wh);
                    unsigned long long wll = pk2f(wl, wl);
                    unsigned long long whh = pk2f(wh, wh);
                    #pragma unroll
                    for (int m = 0; m < 2; m++) acc[i][m] = ffma2(wll, h0[m], acc[i][m]);
                    #pragma unroll
                    for (int m = 0; m < 2; m++) acc[i][m] = ffma2(whh, h1[m], acc[i][m]);
                }
            }
        }
        __syncthreads();
    }

    if (act) {
        #pragma unroll
        for (int i = 0; i < 4; i++) {
            float bias = rb[o0 + i];
            unsigned long long bd = pk2f(bias, bias);
            #pragma unroll
            for (int m = 0; m < 2; m++) {
                F2 r; r.u = add2(acc[i][m], bd);
                *(float2*)&g_h[(b * 64 + o0 + i) * HW + n0 + 2 * pg + 28 * m] = r.f;
            }
        }
    }
}

// ---------------------------------------------------------------------------
// Kernel 2 (fused span GEMM + apply). grid (14,16,4), block 512, 2 CTAs/SM
// -> 32 warps/SM. Per-thread work halved vs R6 to fit 63 regs.
// Phase 1: 392 active, thread = 7kk (kkg=tid/56) x 4px (pxg=tid%56).
// Phase 2: 448 active, thread = 1 pixel-pair (pp=tid>>2) x 4 interleaved
//          channels (ch = (tid&3) + 4i). kern overlays hs buffer.
// ---------------------------------------------------------------------------
__global__ __launch_bounds__(512, 2) void inv_kernel(
    const float* __restrict__ x,
    const float* __restrict__ sw,
    const float* __restrict__ sb,
    float* __restrict__ out)
{
    const int r0 = blockIdx.x * 4;
    const int g  = blockIdx.y;
    const int b  = blockIdx.z;

    extern __shared__ float smem[];
    float* wsp   = smem;              // 3240 (49 x WSTR used)
    float* sbias = smem + 3240;       // 72
    float* hsk   = smem + 3312;       // 14336 : h[64][224], later kern[49][KSTR]
    float* xt    = hsk + 14336;       // 16*624 : x halo 16ch x (10r x 62c)

    const int tid = threadIdx.x;

    // ---- stage span_w into padded rows ----
    {
        const float2* swv = (const float2*)(sw + g * 3136);
        #pragma unroll
        for (int i = 0; i < 4; i++) {
            int e = tid + i * 512;
            if (e < 1568) {
                int kk = e >> 5, c2 = e & 31;
                *(float2*)&wsp[kk * WSTR + 2 * c2] = swv[e];
            }
        }
    }
    if (tid < 49) sbias[tid] = sb[g * 49 + tid];

    // ---- stage h tile ----
    {
        float4* hsv = (float4*)hsk;
        #pragma unroll
        for (int i = 0; i < 7; i++) {
            int e = tid + i * 512;
            int c = e / 56, p4 = e - c * 56;
            hsv[e] = *(const float4*)&g_h[(b * 64 + c) * HW + r0 * 56 + p4 * 4];
        }
    }

    // ---- stage x halo tile ----
    #pragma unroll
    for (int i = 0; i < 20; i++) {
        int e = tid + i * 512;
        if (e < 16 * 620) {
            int cg  = e / 620;
            int rem = e - cg * 620;
            int rr  = rem / 62, cc = rem - rr * 62;
            int gr = r0 + rr - 3;
            int gc = cc - 3;
            float v = 0.f;
            if (gr >= 0 && gr < 56 && gc >= 0 && gc < 56)
                v = x[(b * 256 + g * 16 + cg) * HW + gr * 56 + gc];
            xt[cg * XCH + rem] = v;
        }
    }
    __syncthreads();

    // ---- Phase 1: kern = ws @ hs. thread = 7kk x 4px ----
    const int kkg = tid / 56;        // 0..6 active (tid < 392)
    const int pxg = tid % 56;        // px base = 4*pxg
    const bool p1act = (tid < 392);

    unsigned long long kacc[7][2];
    #pragma unroll
    for (int i = 0; i < 7; i++)
        #pragma unroll
        for (int j = 0; j < 2; j++) kacc[i][j] = 0ull;

    if (p1act) {
        const float* wbase = wsp + kkg * 7 * WSTR;
        #pragma unroll 1
        for (int c2 = 0; c2 < 32; c2++) {
            F4 a, bb;
            a.f  = *(const float4*)&hsk[(2 * c2) * 224 + 4 * pxg];
            bb.f = *(const float4*)&hsk[(2 * c2 + 1) * 224 + 4 * pxg];
            #pragma unroll
            for (int i = 0; i < 7; i++) {
                F2 t; t.f = *(const float2*)&wbase[i * WSTR + 2 * c2];
                float wl, wh;
                unpk2(t.u, wl, wh);
                unsigned long long wll = pk2f(wl, wl);
                unsigned long long whh = pk2f(wh, wh);
                kacc[i][0] = ffma2(wll, a.u[0],  kacc[i][0]);
                kacc[i][1] = ffma2(wll, a.u[1],  kacc[i][1]);
                kacc[i][0] = ffma2(whh, bb.u[0], kacc[i][0]);
                kacc[i][1] = ffma2(whh, bb.u[1], kacc[i][1]);
            }
        }
    }
    __syncthreads();   // all hs reads complete before kern overwrite

    if (p1act) {
        #pragma unroll
        for (int i = 0; i < 7; i++) {
            float bias = sbias[kkg * 7 + i];
            unsigned long long bd = pk2f(bias, bias);
            F4 s;
            s.u[0] = add2(kacc[i][0], bd);
            s.u[1] = add2(kacc[i][1], bd);
            *(float4*)&hsk[(kkg * 7 + i) * KSTR + 4 * pxg] = s.f;
        }
    }
    __syncthreads();

    // ---- Phase 2: apply. thread = 1 pixel-pair x 4 interleaved channels ----
    if (tid < 448) {
        const int pp = tid >> 2;        // 0..111
        const int cq = tid & 3;
        const int lr = pp / 28;         // 0..3
        const int pc = pp - lr * 28;    // 0..27
        const int pix0 = 2 * pp;        // = lr*56 + 2*pc
        const int row  = r0 + lr;

        unsigned long long acc[4];
        #pragma unroll
        for (int i = 0; i < 4; i++) acc[i] = 0ull;

        #pragma unroll 1
        for (int kh = 0; kh < 7; kh++) {
            unsigned long long kc2[7];
            #pragma unroll
            for (int kw = 0; kw < 7; kw++) {
                F2 t; t.f = *(const float2*)&hsk[(kh * 7 + kw) * KSTR + pix0];
                kc2[kw] = t.u;
            }
            #pragma unroll
            for (int i = 0; i < 4; i++) {
                const int ch = cq + 4 * i;           // interleaved channels
                const float* xr = &xt[ch * XCH + (lr + kh) * 62 + 2 * pc];
                F2 P[4];
                #pragma unroll
                for (int s = 0; s < 4; s++) P[s].f = *(const float2*)&xr[2 * s];
                unsigned long long M[3];
                #pragma unroll
                for (int s = 0; s < 3; s++) M[s] = pk2f(P[s].f.y, P[s + 1].f.x);

                acc[i] = ffma2(kc2[0], P[0].u, acc[i]);
                acc[i] = ffma2(kc2[1], M[0],   acc[i]);
                acc[i] = ffma2(kc2[2], P[1].u, acc[i]);
                acc[i] = ffma2(kc2[3], M[1],   acc[i]);
                acc[i] = ffma2(kc2[4], P[2].u, acc[i]);
                acc[i] = ffma2(kc2[5], M[2],   acc[i]);
                acc[i] = ffma2(kc2[6], P[3].u, acc[i]);
            }
        }

        #pragma unroll
        for (int i = 0; i < 4; i++) {
            const int ch = cq + 4 * i;
            F2 r; r.u = acc[i];
            *(float2*)&out[(b * 256 + g * 16 + ch) * HW + row * 56 + 2 * pc] = r.f;
        }
    }
}

extern "C" void kernel_launch(void* const* d_in, const int* in_sizes, int n_in,
                              void* d_out, int out_size)
{
    const float* x  = (const float*)d_in[0];
    const float* rw = (const float*)d_in[1];
    const float* rb = (const float*)d_in[2];
    const float* sw = (const float*)d_in[3];
    const float* sb = (const float*)d_in[4];
    float* out = (float*)d_out;

    const int smem2 = (3240 + 72 + 14336 + 16 * XCH) * sizeof(float); // ~110.5 KB
    cudaFuncSetAttribute(inv_kernel, cudaFuncAttributeMaxDynamicSharedMemorySize, smem2);

    reduce_kernel<<<dim3(56, 4), 256>>>(x, rw, rb);
    inv_kernel<<<dim3(14, 16, 4), 512, smem2>>>(x, sw, sb, out);
}

// round 11
// speedup vs baseline: 1.2598x; 1.2598x over previous
#include <cuda_runtime.h>
#include <cuda_bf16.h>
#include <cstdint>

// Involution: B=4, C=256, G=16, K=7, S=1, P=3, H=W=56
#define HW 3136
#define XCH 634    // xt per-channel stride (floats)
#define KSTR 228   // kern row stride (floats)

// h = reduce(x), stored TRANSPOSED [b][pix][64c] as bf16 hi/lo split pairs
__device__ __nv_bfloat16 g_ht_hi[4 * HW * 64];
__device__ __nv_bfloat16 g_ht_lo[4 * HW * 64];

// ---- f32x2 helpers ----
union F2 { float2 f; unsigned long long u; };
__device__ __forceinline__ unsigned long long pk2f(float lo, float hi) {
    unsigned long long d;
    asm("mov.b64 %0, {%1, %2};" : "=l"(d) : "f"(lo), "f"(hi));
    return d;
}
__device__ __forceinline__ void unpk2(unsigned long long v, float& lo, float& hi) {
    asm("mov.b64 {%0, %1}, %2;" : "=f"(lo), "=f"(hi) : "l"(v));
}
__device__ __forceinline__ unsigned long long ffma2(
    unsigned long long a, unsigned long long b, unsigned long long c) {
    unsigned long long d;
    asm("fma.rn.f32x2 %0, %1, %2, %3;" : "=l"(d) : "l"(a), "l"(b), "l"(c));
    return d;
}

// ---- mma / ldmatrix helpers (sm_80+ PTX; legal on sm_103) ----
__device__ __forceinline__ uint32_t smem_u32(const void* p) {
    uint32_t a;
    asm("{ .reg .u64 t; cvta.to.shared.u64 t, %1; cvt.u32.u64 %0, t; }" : "=r"(a) : "l"(p));
    return a;
}
#define SWZ(o) ((o) ^ (((o) >> 3) & 0x70))
__device__ __forceinline__ void ldsm4(uint32_t* r, uint32_t addr) {
    asm volatile("ldmatrix.sync.aligned.m8n8.x4.shared.b16 {%0,%1,%2,%3}, [%4];"
        : "=r"(r[0]), "=r"(r[1]), "=r"(r[2]), "=r"(r[3]) : "r"(addr));
}
__device__ __forceinline__ void ldsm2(uint32_t* r, uint32_t addr) {
    asm volatile("ldmatrix.sync.aligned.m8n8.x2.shared.b16 {%0,%1}, [%2];"
        : "=r"(r[0]), "=r"(r[1]) : "r"(addr));
}
__device__ __forceinline__ void mma_bf16(float* c, const uint32_t* a, const uint32_t* b) {
    asm volatile("mma.sync.aligned.m16n8k16.row.col.f32.bf16.bf16.f32 "
        "{%0,%1,%2,%3}, {%4,%5,%6,%7}, {%8,%9}, {%0,%1,%2,%3};"
        : "+f"(c[0]), "+f"(c[1]), "+f"(c[2]), "+f"(c[3])
        : "r"(a[0]), "r"(a[1]), "r"(a[2]), "r"(a[3]), "r"(b[0]), "r"(b[1]));
}

// smem byte offsets (inv kernel)
#define SM_WS_HI 0                    // ws bf16 hi: 64 rows x 128B (SW128)
#define SM_WS_LO 8192
#define SM_H_HI  16384                // h bf16 hi: 224 rows x 128B
#define SM_H_LO  45056
#define SM_KERN  16384                // overlay after MMA: 49*KSTR*4 = 44688B <= 57344B
#define SM_XT    73728                // 16ch * XCH * 4 = 40576B
#define SM_SB    114304               // 49 floats
#define SM_TOTAL 114560

// ---------------------------------------------------------------------------
// Kernel 1: h[b,p,o] = sum_c x[b,c,p]*rw[o,c] + rb[o], stored bf16 hi/lo
// grid (28,4), block 256 (224 active). 4 o x 8 px, k-paired, FFMA2.
// ---------------------------------------------------------------------------
__device__ __forceinline__ void store_px_bf16(int b, int px, int o0, const float* v) {
    union { __nv_bfloat16 h[4]; uint2 u; } H, L;
    #pragma unroll
    for (int i = 0; i < 4; i++) {
        H.h[i] = __float2bfloat16(v[i]);
        L.h[i] = __float2bfloat16(v[i] - __bfloat162float(H.h[i]));
    }
    *(uint2*)&g_ht_hi[(b * HW + px) * 64 + o0] = H.u;
    *(uint2*)&g_ht_lo[(b * HW + px) * 64 + o0] = L.u;
}

__global__ __launch_bounds__(256) void reduce_kernel(
    const float* __restrict__ x,
    const float* __restrict__ rw,
    const float* __restrict__ rb)
{
    const int b  = blockIdx.y;
    const int n0 = blockIdx.x * 112;
    __shared__ float ws[64 * 32];
    __shared__ float xs[32 * 112];

    const int tid = threadIdx.x;
    const int og = tid / 14;
    const int pg = tid % 14;
    const int o0 = og * 4;
    const bool act = (tid < 224);

    unsigned long long acc[4][4];
    #pragma unroll
    for (int i = 0; i < 4; i++)
        #pragma unroll
        for (int m = 0; m < 4; m++) acc[i][m] = 0ull;

    for (int kb = 0; kb < 256; kb += 32) {
        #pragma unroll
        for (int i = 0; i < 8; i++) {
            int e = tid + i * 256;
            ws[e] = rw[(e >> 5) * 256 + kb + (e & 31)];
        }
        #pragma unroll
        for (int i = 0; i < 14; i++) {
            int e = tid + i * 256;
            int k = e / 112, p = e - k * 112;
            xs[e] = x[(b * 256 + kb + k) * HW + n0 + p];
        }
        __syncthreads();

        if (act) {
            #pragma unroll 2
            for (int k2 = 0; k2 < 16; k2++) {
                unsigned long long w2[4], h0[4], h1[4];
                #pragma unroll
                for (int i = 0; i < 4; i++) {
                    F2 t; t.f = *(const float2*)&ws[(o0 + i) * 32 + 2 * k2];
                    w2[i] = t.u;
                }
                #pragma unroll
                for (int m = 0; m < 4; m++) {
                    F2 t; t.f = *(const float2*)&xs[(2 * k2) * 112 + 2 * pg + 28 * m];
                    h0[m] = t.u;
                }
                #pragma unroll
                for (int m = 0; m < 4; m++) {
                    F2 t; t.f = *(const float2*)&xs[(2 * k2 + 1) * 112 + 2 * pg + 28 * m];
                    h1[m] = t.u;
                }
                #pragma unroll
                for (int i = 0; i < 4; i++) {
                    float wl, wh;
                    unpk2(w2[i], wl, wh);
                    unsigned long long wll = pk2f(wl, wl);
                    unsigned long long whh = pk2f(wh, wh);
                    #pragma unroll
                    for (int m = 0; m < 4; m++) acc[i][m] = ffma2(wll, h0[m], acc[i][m]);
                    #pragma unroll
                    for (int m = 0; m < 4; m++) acc[i][m] = ffma2(whh, h1[m], acc[i][m]);
                }
            }
        }
        __syncthreads();
    }

    if (act) {
        float bias[4];
        #pragma unroll
        for (int i = 0; i < 4; i++) bias[i] = rb[o0 + i];
        #pragma unroll
        for (int m = 0; m < 4; m++) {
            float v0[4], v1[4];
            #pragma unroll
            for (int i = 0; i < 4; i++) {
                float lo, hi;
                unpk2(acc[i][m], lo, hi);
                v0[i] = lo + bias[i];
                v1[i] = hi + bias[i];
            }
            int px0 = n0 + 2 * pg + 28 * m;
            store_px_bf16(b, px0,     o0, v0);
            store_px_bf16(b, px0 + 1, o0, v1);
        }
    }
}

// ---------------------------------------------------------------------------
// Kernel 2: HMMA span GEMM + fp32 apply. grid (14,16,4), block 256, 2 CTA/SM.
// Phase 1: kern[64][224] = ws[64][64] @ h[224][64]^T via mma.sync m16n8k16
//          bf16 (hi/lo split, 3 accumulating GEMMs). Warp w: m-tile w>>1,
//          n-half w&1 (14 n-tiles of 8 px). ldmatrix from SW128 smem.
// Phase 2: R6 apply (4px x 4 interleaved ch per thread, FFMA2).
// ---------------------------------------------------------------------------
__global__ __launch_bounds__(256, 2) void inv_kernel(
    const float* __restrict__ x,
    const float* __restrict__ sw,
    const float* __restrict__ sb,
    float* __restrict__ out)
{
    const int r0 = blockIdx.x * 4;
    const int g  = blockIdx.y;
    const int b  = blockIdx.z;

    extern __shared__ char smem[];
    const int tid = threadIdx.x;
    const uint32_t sbase = smem_u32(smem);

    float* kernsm = (float*)(smem + SM_KERN);
    float* xt     = (float*)(smem + SM_XT);
    float* sbias  = (float*)(smem + SM_SB);

    // ---- stage ws -> bf16 hi/lo (SW128 swizzled rows of 128B) ----
    for (int e = tid; e < 3136; e += 256) {
        int r = e >> 6, c = e & 63;
        float v = sw[g * 3136 + e];
        __nv_bfloat16 h = __float2bfloat16(v);
        __nv_bfloat16 l = __float2bfloat16(v - __bfloat162float(h));
        int swo = SWZ(r * 128 + c * 2);
        *(__nv_bfloat16*)(smem + SM_WS_HI + swo) = h;
        *(__nv_bfloat16*)(smem + SM_WS_LO + swo) = l;
    }
    if (tid < 49) sbias[tid] = sb[g * 49 + tid];

    // ---- stage h -> bf16 hi/lo (uint4 chunks, SW128 swizzled) ----
    {
        const uint4* bh = (const uint4*)(g_ht_hi + ((size_t)b * HW + r0 * 56) * 64);
        const uint4* bl = (const uint4*)(g_ht_lo + ((size_t)b * HW + r0 * 56) * 64);
        for (int e = tid; e < 1792; e += 256) {
            int swo = SWZ(e * 16);
            *(uint4*)(smem + SM_H_HI + swo) = bh[e];
            *(uint4*)(smem + SM_H_LO + swo) = bl[e];
        }
    }

    // ---- stage x halo tile: 16 ch x 10r x 62c ----
    #pragma unroll
    for (int i = 0; i < 39; i++) {
        int e = tid + i * 256;
        if (e < 16 * 620) {
            int cg  = e / 620;
            int rem = e - cg * 620;
            int rr  = rem / 62, cc = rem - rr * 62;
            int gr = r0 + rr - 3;
            int gc = cc - 3;
            float v = 0.f;
            if (gr >= 0 && gr < 56 && gc >= 0 && gc < 56)
                v = x[(b * 256 + g * 16 + cg) * HW + gr * 56 + gc];
            xt[cg * XCH + rem] = v;
        }
    }
    __syncthreads();

    // ---- Phase 1: HMMA GEMM ----
    const int wrp = tid >> 5, lane = tid & 31;
    const int mt = wrp >> 1;        // m-tile 0..3 (rows mt*16..+15; valid kk < 49)
    const int nh = wrp & 1;         // n half: 14 tiles of 8 px

    float acc[14][4];
    #pragma unroll
    for (int j = 0; j < 14; j++)
        #pragma unroll
        for (int q = 0; q < 4; q++) acc[j][q] = 0.f;

    const uint32_t a_off = (uint32_t)((mt * 16 + (lane & 15)) * 128 + ((lane & 16) ? 16 : 0));
    const uint32_t b_lane = (uint32_t)((lane & 7) * 128 + ((lane & 8) ? 16 : 0));

    #pragma unroll
    for (int kt = 0; kt < 4; kt++) {
        uint32_t ahi[4], alo[4];
        ldsm4(ahi, sbase + SM_WS_HI + SWZ(a_off + kt * 32));
        ldsm4(alo, sbase + SM_WS_LO + SWZ(a_off + kt * 32));
        #pragma unroll
        for (int j = 0; j < 14; j++) {
            uint32_t boff = SWZ(b_lane + (uint32_t)((nh * 14 + j) * 1024) + kt * 32);
            uint32_t bh[2], bl[2];
            ldsm2(bh, sbase + SM_H_HI + boff);
            ldsm2(bl, sbase + SM_H_LO + boff);
            mma_bf16(acc[j], ahi, bh);
            mma_bf16(acc[j], ahi, bl);
            mma_bf16(acc[j], alo, bh);
        }
    }
    __syncthreads();   // all ldmatrix reads of h done before kern overlay writes

    // ---- epilogue: fragments + bias -> kern smem ----
    {
        const int gq = lane >> 2, tig = lane & 3;
        const int kk0 = mt * 16 + gq;
        const int kk1 = kk0 + 8;
        const float b0 = (kk0 < 49) ? sbias[kk0] : 0.f;
        const float b1 = (kk1 < 49) ? sbias[kk1] : 0.f;
        #pragma unroll
        for (int j = 0; j < 14; j++) {
            const int px = (nh * 14 + j) * 8 + 2 * tig;
            if (kk0 < 49) {
                float2 v = {acc[j][0] + b0, acc[j][1] + b0};
                *(float2*)&kernsm[kk0 * KSTR + px] = v;
            }
            if (kk1 < 49) {
                float2 v = {acc[j][2] + b1, acc[j][3] + b1};
                *(float2*)&kernsm[kk1 * KSTR + px] = v;
            }
        }
    }
    __syncthreads();

    // ---- Phase 2: apply (R6). thread = 4 px x 4 interleaved channels ----
    if (tid < 224) {
        const int pd  = tid >> 2;          // 0..55
        const int cq  = tid & 3;
        const int lr  = pd / 14;
        const int pc4 = pd - lr * 14;
        const int pix0 = 4 * pd;           // = lr*56 + 4*pc4
        const int col0 = 4 * pc4;
        const int row  = r0 + lr;

        unsigned long long acc2[4][2];
        #pragma unroll
        for (int i = 0; i < 4; i++)
            #pragma unroll
            for (int j = 0; j < 2; j++) acc2[i][j] = 0ull;

        #pragma unroll 1
        for (int kh = 0; kh < 7; kh++) {
            unsigned long long kc2[7][2];
            #pragma unroll
            for (int kw = 0; kw < 7; kw++)
                #pragma unroll
                for (int j = 0; j < 2; j++) {
                    F2 t; t.f = *(const float2*)&kernsm[(kh * 7 + kw) * KSTR + pix0 + 2 * j];
                    kc2[kw][j] = t.u;
                }

            #pragma unroll
            for (int i = 0; i < 4; i++) {
                const int ch = cq + 4 * i;           // interleaved channels
                const float* xr = &xt[ch * XCH + (lr + kh) * 62 + col0];
                F2 P[5];
                #pragma unroll
                for (int s = 0; s < 5; s++) P[s].f = *(const float2*)&xr[2 * s];
                unsigned long long M[4];
                #pragma unroll
                for (int s = 0; s < 4; s++) M[s] = pk2f(P[s].f.y, P[s + 1].f.x);

                acc2[i][0] = ffma2(kc2[0][0], P[0].u, acc2[i][0]);
                acc2[i][0] = ffma2(kc2[1][0], M[0],   acc2[i][0]);
                acc2[i][0] = ffma2(kc2[2][0], P[1].u, acc2[i][0]);
                acc2[i][0] = ffma2(kc2[3][0], M[1],   acc2[i][0]);
                acc2[i][0] = ffma2(kc2[4][0], P[2].u, acc2[i][0]);
                acc2[i][0] = ffma2(kc2[5][0], M[2],   acc2[i][0]);
                acc2[i][0] = ffma2(kc2[6][0], P[3].u, acc2[i][0]);

                acc2[i][1] = ffma2(kc2[0][1], P[1].u, acc2[i][1]);
                acc2[i][1] = ffma2(kc2[1][1], M[1],   acc2[i][1]);
                acc2[i][1] = ffma2(kc2[2][1], P[2].u, acc2[i][1]);
                acc2[i][1] = ffma2(kc2[3][1], M[2],   acc2[i][1]);
                acc2[i][1] = ffma2(kc2[4][1], P[3].u, acc2[i][1]);
                acc2[i][1] = ffma2(kc2[5][1], M[3],   acc2[i][1]);
                acc2[i][1] = ffma2(kc2[6][1], P[4].u, acc2[i][1]);
            }
        }

        #pragma unroll
        for (int i = 0; i < 4; i++) {
            const int ch = cq + 4 * i;
            #pragma unroll
            for (int j = 0; j < 2; j++) {
                F2 r; r.u = acc2[i][j];
                *(float2*)&out[(b * 256 + g * 16 + ch) * HW + row * 56 + col0 + 2 * j] = r.f;
            }
        }
    }
}

extern "C" void kernel_launch(void* const* d_in, const int* in_sizes, int n_in,
                              void* d_out, int out_size)
{
    const float* x  = (const float*)d_in[0];
    const float* rw = (const float*)d_in[1];
    const float* rb = (const float*)d_in[2];
    const float* sw = (const float*)d_in[3];
    const float* sb = (const float*)d_in[4];
    float* out = (float*)d_out;

    cudaFuncSetAttribute(inv_kernel, cudaFuncAttributeMaxDynamicSharedMemorySize, SM_TOTAL);

    reduce_kernel<<<dim3(28, 4), 256>>>(x, rw, rb);
    inv_kernel<<<dim3(14, 16, 4), 256, SM_TOTAL>>>(x, sw, sb, out);
}

// round 12
// speedup vs baseline: 1.5183x; 1.2052x over previous
#include <cuda_runtime.h>
#include <cuda_bf16.h>
#include <cstdint>

// Involution: B=4, C=256, G=16, K=7, S=1, P=3, H=W=56
#define HW 3136
#define XCH 634    // xt per-channel stride (floats)
#define KSTR 228   // kern row stride (floats)

// h^T[b][px][64o] bf16 hi/lo, rows of 128B stored PRE-SWIZZLED (SW128)
__device__ uint4 g_ht_hi[4 * HW * 8];    // 4*HW rows * 128B
__device__ uint4 g_ht_lo[4 * HW * 8];
// weight images: bf16 hi/lo, SW128 pre-swizzled rows of 128B
__device__ uint4 g_rw_img_hi[2048];      // [4 chunks][64 o][64 c] = 32KB
__device__ uint4 g_rw_img_lo[2048];
__device__ uint4 g_sw_img_hi[8192];      // [16 g][64 row][64 c] = 128KB
__device__ uint4 g_sw_img_lo[8192];

// ---- f32x2 helpers ----
union F2 { float2 f; unsigned long long u; };
__device__ __forceinline__ unsigned long long pk2f(float lo, float hi) {
    unsigned long long d;
    asm("mov.b64 %0, {%1, %2};" : "=l"(d) : "f"(lo), "f"(hi));
    return d;
}
__device__ __forceinline__ unsigned long long ffma2(
    unsigned long long a, unsigned long long b, unsigned long long c) {
    unsigned long long d;
    asm("fma.rn.f32x2 %0, %1, %2, %3;" : "=l"(d) : "l"(a), "l"(b), "l"(c));
    return d;
}

// ---- mma / ldmatrix helpers ----
__device__ __forceinline__ uint32_t smem_u32(const void* p) {
    uint32_t a;
    asm("{ .reg .u64 t; cvta.to.shared.u64 t, %1; cvt.u32.u64 %0, t; }" : "=r"(a) : "l"(p));
    return a;
}
#define SWZ(o) ((o) ^ (((o) >> 3) & 0x70))
__device__ __forceinline__ void ldsm4(uint32_t* r, uint32_t addr) {
    asm volatile("ldmatrix.sync.aligned.m8n8.x4.shared.b16 {%0,%1,%2,%3}, [%4];"
        : "=r"(r[0]), "=r"(r[1]), "=r"(r[2]), "=r"(r[3]) : "r"(addr));
}
__device__ __forceinline__ void ldsm2(uint32_t* r, uint32_t addr) {
    asm volatile("ldmatrix.sync.aligned.m8n8.x2.shared.b16 {%0,%1}, [%2];"
        : "=r"(r[0]), "=r"(r[1]) : "r"(addr));
}
__device__ __forceinline__ void ldsm2t(uint32_t* r, uint32_t addr) {
    asm volatile("ldmatrix.sync.aligned.m8n8.x2.trans.shared.b16 {%0,%1}, [%2];"
        : "=r"(r[0]), "=r"(r[1]) : "r"(addr));
}
__device__ __forceinline__ void mma_bf16(float* c, const uint32_t* a, const uint32_t* b) {
    asm volatile("mma.sync.aligned.m16n8k16.row.col.f32.bf16.bf16.f32 "
        "{%0,%1,%2,%3}, {%4,%5,%6,%7}, {%8,%9}, {%0,%1,%2,%3};"
        : "+f"(c[0]), "+f"(c[1]), "+f"(c[2]), "+f"(c[3])
        : "r"(a[0]), "r"(a[1]), "r"(a[2]), "r"(a[3]), "r"(b[0]), "r"(b[1]));
}

// ---------------------------------------------------------------------------
// prep: build bf16 hi/lo SW128-swizzled weight images (one-time, tiny)
// ---------------------------------------------------------------------------
__global__ void prep_kernel(const float* __restrict__ rw, const float* __restrict__ sw)
{
    int idx = blockIdx.x * 256 + threadIdx.x;
    if (idx < 16384) {                 // rw [64][256] -> [4][64][64]
        int o = idx >> 8, c = idx & 255;
        int chunk = c >> 6, cl = c & 63;
        float v = rw[idx];
        __nv_bfloat16 h = __float2bfloat16(v);
        __nv_bfloat16 l = __float2bfloat16(v - __bfloat162float(h));
        int byte = chunk * 8192 + o * 128 + ((cl * 2) ^ ((o & 7) << 4));
        *(__nv_bfloat16*)((char*)g_rw_img_hi + byte) = h;
        *(__nv_bfloat16*)((char*)g_rw_img_lo + byte) = l;
    }
    int idx2 = idx - 16384;
    if (idx2 >= 0 && idx2 < 65536) {   // span_w [16][49][64] -> [16][64][64] (rows 49-63 zero)
        int g = idx2 >> 12, rem = idx2 & 4095;
        int r = rem >> 6, c = rem & 63;
        float v = (r < 49) ? sw[g * 3136 + r * 64 + c] : 0.f;
        __nv_bfloat16 h = __float2bfloat16(v);
        __nv_bfloat16 l = __float2bfloat16(v - __bfloat162float(h));
        int byte = g * 8192 + r * 128 + ((c * 2) ^ ((r & 7) << 4));
        *(__nv_bfloat16*)((char*)g_sw_img_hi + byte) = h;
        *(__nv_bfloat16*)((char*)g_sw_img_lo + byte) = l;
    }
}

// ---------------------------------------------------------------------------
// Kernel 1 (HMMA): h^T[b][px][o] = rw @ x, grid (28,4), 256 thr.
// A = rw [64o][256c] (chunked images), B = x [c][px] via ldmatrix.trans.
// ---------------------------------------------------------------------------
#define R_RWHI 0
#define R_RWLO 32768
#define R_XBHI 65536               // 256 rows x 240B = 61440
#define R_XBLO 126976
#define R_T    65536               // overlay: 112*68*4 = 30464
#define R_RB   188416              // 64 floats
#define R_TOTAL 188672

__global__ __launch_bounds__(256) void reduce_mma(
    const float* __restrict__ x,
    const float* __restrict__ rb)
{
    const int b  = blockIdx.y;
    const int n0 = blockIdx.x * 112;
    extern __shared__ char smem[];
    const int tid = threadIdx.x;
    const uint32_t sbase = smem_u32(smem);
    float* rbs = (float*)(smem + R_RB);

    // weight image copy (pure memcpy, pre-swizzled)
    {
        uint4* sh = (uint4*)(smem + R_RWHI);
        uint4* sl = (uint4*)(smem + R_RWLO);
        #pragma unroll
        for (int i = 0; i < 8; i++) {
            int e = tid + i * 256;
            sh[e] = g_rw_img_hi[e];
            sl[e] = g_rw_img_lo[e];
        }
    }
    if (tid < 64) rbs[tid] = rb[tid];

    // stage x -> bf16 hi/lo [c][px] rows of 240B (dense, coalesced)
    for (int e4 = tid; e4 < 7168; e4 += 256) {
        int c = e4 / 28, p4 = (e4 - c * 28) * 4;
        float4 v = *(const float4*)&x[(size_t)(b * 256 + c) * HW + n0 + p4];
        __nv_bfloat162 h0 = __floats2bfloat162_rn(v.x, v.y);
        __nv_bfloat162 h1 = __floats2bfloat162_rn(v.z, v.w);
        float r0 = v.x - __bfloat162float(h0.x);
        float r1 = v.y - __bfloat162float(h0.y);
        float r2 = v.z - __bfloat162float(h1.x);
        float r3 = v.w - __bfloat162float(h1.y);
        __nv_bfloat162 l0 = __floats2bfloat162_rn(r0, r1);
        __nv_bfloat162 l1 = __floats2bfloat162_rn(r2, r3);
        union { __nv_bfloat162 b2[2]; uint2 u; } H, L;
        H.b2[0] = h0; H.b2[1] = h1; L.b2[0] = l0; L.b2[1] = l1;
        *(uint2*)(smem + R_XBHI + c * 240 + p4 * 2) = H.u;
        *(uint2*)(smem + R_XBLO + c * 240 + p4 * 2) = L.u;
    }
    __syncthreads();

    // GEMM: 8 warps = 4 mt x 2 nh; acc[7 n-tiles][4]
    const int wrp = tid >> 5, lane = tid & 31;
    const int mt = wrp >> 1, nh = wrp & 1;
    float acc[7][4];
    #pragma unroll
    for (int j = 0; j < 7; j++)
        #pragma unroll
        for (int q = 0; q < 4; q++) acc[j][q] = 0.f;

    const uint32_t a_off = (uint32_t)((mt * 16 + (lane & 15)) * 128 + ((lane & 16) ? 16 : 0));

    #pragma unroll 1
    for (int kt = 0; kt < 16; kt++) {
        const int q = kt >> 2, ktl = kt & 3;
        uint32_t ahi[4], alo[4];
        ldsm4(ahi, sbase + R_RWHI + q * 8192 + SWZ(a_off + ktl * 32));
        ldsm4(alo, sbase + R_RWLO + q * 8192 + SWZ(a_off + ktl * 32));
        const uint32_t brow = (uint32_t)((kt * 16 + (lane & 15)) * 240);
        #pragma unroll
        for (int j = 0; j < 7; j++) {
            const uint32_t pxo = (uint32_t)(((nh * 7 + j) * 8) * 2);
            uint32_t bh[2], bl[2];
            ldsm2t(bh, sbase + R_XBHI + brow + pxo);
            ldsm2t(bl, sbase + R_XBLO + brow + pxo);
            mma_bf16(acc[j], ahi, bh);
            mma_bf16(acc[j], ahi, bl);
            mma_bf16(acc[j], alo, bh);
        }
    }
    __syncthreads();   // all XB reads done before T overlay

    // transpose through T[112px][68]
    {
        float* T = (float*)(smem + R_T);
        const int gq = lane >> 2, tig = lane & 3;
        const int o = mt * 16 + gq;
        #pragma unroll
        for (int j = 0; j < 7; j++) {
            const int px0 = (nh * 7 + j) * 8 + 2 * tig;
            T[px0 * 68 + o]           = acc[j][0];
            T[(px0 + 1) * 68 + o]     = acc[j][1];
            T[px0 * 68 + o + 8]       = acc[j][2];
            T[(px0 + 1) * 68 + o + 8] = acc[j][3];
        }
    }
    __syncthreads();

    // final: +bias, bf16 hi/lo, pre-swizzled STG
    {
        const float* T = (const float*)(smem + R_T);
        for (int e2 = tid; e2 < 1792; e2 += 256) {
            int px = e2 >> 4, o4 = (e2 & 15) * 4;
            float4 v = *(const float4*)&T[px * 68 + o4];
            v.x += rbs[o4]; v.y += rbs[o4 + 1]; v.z += rbs[o4 + 2]; v.w += rbs[o4 + 3];
            __nv_bfloat162 h0 = __floats2bfloat162_rn(v.x, v.y);
            __nv_bfloat162 h1 = __floats2bfloat162_rn(v.z, v.w);
            __nv_bfloat162 l0 = __floats2bfloat162_rn(v.x - __bfloat162float(h0.x),
                                                      v.y - __bfloat162float(h0.y));
            __nv_bfloat162 l1 = __floats2bfloat162_rn(v.z - __bfloat162float(h1.x),
                                                      v.w - __bfloat162float(h1.y));
            union { __nv_bfloat162 b2[2]; uint2 u; } H, L;
            H.b2[0] = h0; H.b2[1] = h1; L.b2[0] = l0; L.b2[1] = l1;
            size_t rowb = (size_t)(b * HW + n0 + px) * 128;
            int swo = (o4 * 2) ^ (((n0 + px) & 7) << 4);
            *(uint2*)((char*)g_ht_hi + rowb + swo) = H.u;
            *(uint2*)((char*)g_ht_lo + rowb + swo) = L.u;
        }
    }
}

// ---------------------------------------------------------------------------
// Kernel 2: HMMA span GEMM + fp32 apply (R11 structure, leaner staging).
// ---------------------------------------------------------------------------
#define SM_WS_HI 0
#define SM_WS_LO 8192
#define SM_H_HI  16384
#define SM_H_LO  45056
#define SM_KERN  16384
#define SM_XT    73728
#define SM_SB    114304
#define SM_TOTAL 114560

__global__ __launch_bounds__(256, 2) void inv_kernel(
    const float* __restrict__ x,
    const float* __restrict__ sw,
    const float* __restrict__ sb,
    float* __restrict__ out)
{
    const int r0 = blockIdx.x * 4;
    const int g  = blockIdx.y;
    const int b  = blockIdx.z;

    extern __shared__ char smem[];
    const int tid = threadIdx.x;
    const uint32_t sbase = smem_u32(smem);
    const int wrp = tid >> 5, lane = tid & 31;

    float* kernsm = (float*)(smem + SM_KERN);
    float* xt     = (float*)(smem + SM_XT);
    float* sbias  = (float*)(smem + SM_SB);

    // ---- ws image copy (pre-swizzled) ----
    {
        uint4* sh = (uint4*)(smem + SM_WS_HI);
        uint4* sl = (uint4*)(smem + SM_WS_LO);
        const uint4* gh = g_sw_img_hi + g * 512;
        const uint4* gl = g_sw_img_lo + g * 512;
        #pragma unroll
        for (int i = 0; i < 2; i++) {
            int e = tid + i * 256;
            sh[e] = gh[e];
            sl[e] = gl[e];
        }
    }
    if (tid < 49) sbias[tid] = sb[g * 49 + tid];

    // ---- h tile copy (pre-swizzled rows) ----
    {
        const uint4* bh = g_ht_hi + (size_t)(b * HW + r0 * 56) * 8;
        const uint4* bl = g_ht_lo + (size_t)(b * HW + r0 * 56) * 8;
        uint4* sh = (uint4*)(smem + SM_H_HI);
        uint4* sl = (uint4*)(smem + SM_H_LO);
        #pragma unroll
        for (int i = 0; i < 7; i++) {
            int e = tid + i * 256;
            sh[e] = bh[e];
            sl[e] = bl[e];
        }
    }

    // ---- x halo tile: job = (ch, row), lanes = cols ----
    {
        #pragma unroll 1
        for (int it = 0; it < 20; it++) {
            int job = it * 8 + wrp;            // 0..159
            int ch = job / 10, rr = job - ch * 10;
            int gr = r0 + rr - 3;
            bool rok = (gr >= 0) && (gr < 56);
            const float* xrow = &x[(size_t)(b * 256 + g * 16 + ch) * HW + gr * 56];
            float* drow = &xt[ch * XCH + rr * 62];
            int c0 = lane, c1 = lane + 32;
            float v0 = 0.f, v1 = 0.f;
            int g0 = c0 - 3, g1 = c1 - 3;
            if (rok && g0 >= 0 && g0 < 56) v0 = xrow[g0];
            if (rok && g1 < 56 && c1 < 62) v1 = xrow[g1];
            drow[c0] = v0;
            if (c1 < 62) drow[c1] = v1;
        }
    }
    __syncthreads();

    // ---- Phase 1: HMMA GEMM kern[64][224] ----
    const int mt = wrp >> 1;
    const int nh = wrp & 1;

    float acc[14][4];
    #pragma unroll
    for (int j = 0; j < 14; j++)
        #pragma unroll
        for (int q = 0; q < 4; q++) acc[j][q] = 0.f;

    const uint32_t a_off = (uint32_t)((mt * 16 + (lane & 15)) * 128 + ((lane & 16) ? 16 : 0));
    const uint32_t b_lane = (uint32_t)((lane & 7) * 128 + ((lane & 8) ? 16 : 0));

    #pragma unroll
    for (int kt = 0; kt < 4; kt++) {
        uint32_t ahi[4], alo[4];
        ldsm4(ahi, sbase + SM_WS_HI + SWZ(a_off + kt * 32));
        ldsm4(alo, sbase + SM_WS_LO + SWZ(a_off + kt * 32));
        #pragma unroll
        for (int j = 0; j < 14; j++) {
            uint32_t boff = SWZ(b_lane + (uint32_t)((nh * 14 + j) * 1024) + kt * 32);
            uint32_t bh[2], bl[2];
            ldsm2(bh, sbase + SM_H_HI + boff);
            ldsm2(bl, sbase + SM_H_LO + boff);
            mma_bf16(acc[j], ahi, bh);
            mma_bf16(acc[j], ahi, bl);
            mma_bf16(acc[j], alo, bh);
        }
    }
    __syncthreads();   // all h reads done before kern overlay writes

    // ---- epilogue: fragments + bias -> kern smem ----
    {
        const int gq = lane >> 2, tig = lane & 3;
        const int kk0 = mt * 16 + gq;
        const int kk1 = kk0 + 8;
        const float b0 = (kk0 < 49) ? sbias[kk0] : 0.f;
        const float b1 = (kk1 < 49) ? sbias[kk1] : 0.f;
        #pragma unroll
        for (int j = 0; j < 14; j++) {
            const int px = (nh * 14 + j) * 8 + 2 * tig;
            if (kk0 < 49) {
                float2 v = {acc[j][0] + b0, acc[j][1] + b0};
                *(float2*)&kernsm[kk0 * KSTR + px] = v;
            }
            if (kk1 < 49) {
                float2 v = {acc[j][2] + b1, acc[j][3] + b1};
                *(float2*)&kernsm[kk1 * KSTR + px] = v;
            }
        }
    }
    __syncthreads();

    // ---- Phase 2: apply. thread = 4 px x 4 interleaved channels ----
    if (tid < 224) {
        const int pd  = tid >> 2;
        const int cq  = tid & 3;
        const int lr  = pd / 14;
        const int pc4 = pd - lr * 14;
        const int pix0 = 4 * pd;
        const int col0 = 4 * pc4;
        const int row  = r0 + lr;

        unsigned long long acc2[4][2];
        #pragma unroll
        for (int i = 0; i < 4; i++)
            #pragma unroll
            for (int j = 0; j < 2; j++) acc2[i][j] = 0ull;

        #pragma unroll 1
        for (int kh = 0; kh < 7; kh++) {
            unsigned long long kc2[7][2];
            #pragma unroll
            for (int kw = 0; kw < 7; kw++)
                #pragma unroll
                for (int j = 0; j < 2; j++) {
                    F2 t; t.f = *(const float2*)&kernsm[(kh * 7 + kw) * KSTR + pix0 + 2 * j];
                    kc2[kw][j] = t.u;
                }

            #pragma unroll
            for (int i = 0; i < 4; i++) {
                const int ch = cq + 4 * i;
                const float* xr = &xt[ch * XCH + (lr + kh) * 62 + col0];
                F2 P[5];
                #pragma unroll
                for (int s = 0; s < 5; s++) P[s].f = *(const float2*)&xr[2 * s];
                unsigned long long M[4];
                #pragma unroll
                for (int s = 0; s < 4; s++) M[s] = pk2f(P[s].f.y, P[s + 1].f.x);

                acc2[i][0] = ffma2(kc2[0][0], P[0].u, acc2[i][0]);
                acc2[i][0] = ffma2(kc2[1][0], M[0],   acc2[i][0]);
                acc2[i][0] = ffma2(kc2[2][0], P[1].u, acc2[i][0]);
                acc2[i][0] = ffma2(kc2[3][0], M[1],   acc2[i][0]);
                acc2[i][0] = ffma2(kc2[4][0], P[2].u, acc2[i][0]);
                acc2[i][0] = ffma2(kc2[5][0], M[2],   acc2[i][0]);
                acc2[i][0] = ffma2(kc2[6][0], P[3].u, acc2[i][0]);

                acc2[i][1] = ffma2(kc2[0][1], P[1].u, acc2[i][1]);
                acc2[i][1] = ffma2(kc2[1][1], M[1],   acc2[i][1]);
                acc2[i][1] = ffma2(kc2[2][1], P[2].u, acc2[i][1]);
                acc2[i][1] = ffma2(kc2[3][1], M[2],   acc2[i][1]);
                acc2[i][1] = ffma2(kc2[4][1], P[3].u, acc2[i][1]);
                acc2[i][1] = ffma2(kc2[5][1], M[3],   acc2[i][1]);
                acc2[i][1] = ffma2(kc2[6][1], P[4].u, acc2[i][1]);
            }
        }

        #pragma unroll
        for (int i = 0; i < 4; i++) {
            const int ch = cq + 4 * i;
            #pragma unroll
            for (int j = 0; j < 2; j++) {
                F2 r; r.u = acc2[i][j];
                *(float2*)&out[(size_t)(b * 256 + g * 16 + ch) * HW + row * 56 + col0 + 2 * j] = r.f;
            }
        }
    }
}

extern "C" void kernel_launch(void* const* d_in, const int* in_sizes, int n_in,
                              void* d_out, int out_size)
{
    const float* x  = (const float*)d_in[0];
    const float* rw = (const float*)d_in[1];
    const float* rb = (const float*)d_in[2];
    const float* sw = (const float*)d_in[3];
    const float* sb = (const float*)d_in[4];
    float* out = (float*)d_out;

    cudaFuncSetAttribute(reduce_mma, cudaFuncAttributeMaxDynamicSharedMemorySize, R_TOTAL);
    cudaFuncSetAttribute(inv_kernel, cudaFuncAttributeMaxDynamicSharedMemorySize, SM_TOTAL);

    prep_kernel<<<320, 256>>>(rw, sw);
    reduce_mma<<<dim3(28, 4), 256, R_TOTAL>>>(x, rb);
    inv_kernel<<<dim3(14, 16, 4), 256, SM_TOTAL>>>(x, sw, sb, out);
}

// round 13
// speedup vs baseline: 1.5749x; 1.0373x over previous
#include <cuda_runtime.h>
#include <cuda_bf16.h>
#include <cstdint>

// Involution: B=4, C=256, G=16, K=7, S=1, P=3, H=W=56
#define HW 3136
#define XCH 634    // xt per-channel stride (floats)
#define KSTR 228   // kern row stride (floats)

// h^T[b][px][64o] bf16 hi/lo, rows of 128B stored PRE-SWIZZLED (SW128)
__device__ uint4 g_ht_hi[4 * HW * 8];    // 4*HW rows * 128B
__device__ uint4 g_ht_lo[4 * HW * 8];
// span_w image: bf16 hi/lo, SW128 pre-swizzled rows of 128B (built by reduce_mma)
__device__ uint4 g_sw_img_hi[8192];      // [16 g][64 row][64 c] = 128KB
__device__ uint4 g_sw_img_lo[8192];

// ---- f32x2 helpers ----
union F2 { float2 f; unsigned long long u; };
__device__ __forceinline__ unsigned long long pk2f(float lo, float hi) {
    unsigned long long d;
    asm("mov.b64 %0, {%1, %2};" : "=l"(d) : "f"(lo), "f"(hi));
    return d;
}
__device__ __forceinline__ unsigned long long ffma2(
    unsigned long long a, unsigned long long b, unsigned long long c) {
    unsigned long long d;
    asm("fma.rn.f32x2 %0, %1, %2, %3;" : "=l"(d) : "l"(a), "l"(b), "l"(c));
    return d;
}

// ---- mma / ldmatrix helpers ----
__device__ __forceinline__ uint32_t smem_u32(const void* p) {
    uint32_t a;
    asm("{ .reg .u64 t; cvta.to.shared.u64 t, %1; cvt.u32.u64 %0, t; }" : "=r"(a) : "l"(p));
    return a;
}
#define SWZ(o) ((o) ^ (((o) >> 3) & 0x70))
__device__ __forceinline__ void ldsm4(uint32_t* r, uint32_t addr) {
    asm volatile("ldmatrix.sync.aligned.m8n8.x4.shared.b16 {%0,%1,%2,%3}, [%4];"
        : "=r"(r[0]), "=r"(r[1]), "=r"(r[2]), "=r"(r[3]) : "r"(addr));
}
__device__ __forceinline__ void ldsm2(uint32_t* r, uint32_t addr) {
    asm volatile("ldmatrix.sync.aligned.m8n8.x2.shared.b16 {%0,%1}, [%2];"
        : "=r"(r[0]), "=r"(r[1]) : "r"(addr));
}
__device__ __forceinline__ void ldsm2t(uint32_t* r, uint32_t addr) {
    asm volatile("ldmatrix.sync.aligned.m8n8.x2.trans.shared.b16 {%0,%1}, [%2];"
        : "=r"(r[0]), "=r"(r[1]) : "r"(addr));
}
__device__ __forceinline__ void mma_bf16(float* c, const uint32_t* a, const uint32_t* b) {
    asm volatile("mma.sync.aligned.m16n8k16.row.col.f32.bf16.bf16.f32 "
        "{%0,%1,%2,%3}, {%4,%5,%6,%7}, {%8,%9}, {%0,%1,%2,%3};"
        : "+f"(c[0]), "+f"(c[1]), "+f"(c[2]), "+f"(c[3])
        : "r"(a[0]), "r"(a[1]), "r"(a[2]), "r"(a[3]), "r"(b[0]), "r"(b[1]));
}

__device__ __forceinline__ void split_bf16x4(const float4& v, uint2& H, uint2& L) {
    __nv_bfloat162 h0 = __floats2bfloat162_rn(v.x, v.y);
    __nv_bfloat162 h1 = __floats2bfloat162_rn(v.z, v.w);
    __nv_bfloat162 l0 = __floats2bfloat162_rn(v.x - __bfloat162float(h0.x),
                                              v.y - __bfloat162float(h0.y));
    __nv_bfloat162 l1 = __floats2bfloat162_rn(v.z - __bfloat162float(h1.x),
                                              v.w - __bfloat162float(h1.y));
    union { __nv_bfloat162 b2[2]; uint2 u; } t;
    t.b2[0] = h0; t.b2[1] = h1; H = t.u;
    t.b2[0] = l0; t.b2[1] = l1; L = t.u;
}

// ---------------------------------------------------------------------------
// Kernel 1 (HMMA): h^T[b][px][o] = rw @ x, grid (28,4), 256 thr.
// Also: converts rw inline into smem (no prep launch) and builds the
// span_w global image for inv (spread over all 28672 threads).
// ---------------------------------------------------------------------------
#define R_RWHI 0
#define R_RWLO 32768
#define R_XBHI 65536               // 256 rows x 240B = 61440
#define R_XBLO 126976
#define R_T    65536               // overlay: 112*68*4 = 30464
#define R_RB   188416              // 64 floats
#define R_TOTAL 188672

__global__ __launch_bounds__(256) void reduce_mma(
    const float* __restrict__ x,
    const float* __restrict__ rw,
    const float* __restrict__ sw,
    const float* __restrict__ rb)
{
    const int b  = blockIdx.y;
    const int n0 = blockIdx.x * 112;
    extern __shared__ char smem[];
    const int tid = threadIdx.x;
    const uint32_t sbase = smem_u32(smem);
    float* rbs = (float*)(smem + R_RB);

    // rw -> smem bf16 hi/lo, SW128 swizzled (inline conversion, coalesced)
    #pragma unroll
    for (int i = 0; i < 16; i++) {
        int e4 = tid + i * 256;            // float4 index in [0, 4096)
        int o = e4 >> 6;                   // 64 float4 per o-row
        int c = (e4 & 63) * 4;             // 0..252, multiple of 4
        int chunk = c >> 6, cl = c & 63;
        float4 v = *(const float4*)&rw[e4 * 4];
        uint2 H, L;
        split_bf16x4(v, H, L);
        int byte = chunk * 8192 + o * 128 + ((cl * 2) ^ ((o & 7) << 4));
        *(uint2*)(smem + R_RWHI + byte) = H;
        *(uint2*)(smem + R_RWLO + byte) = L;
    }
    if (tid < 64) rbs[tid] = rb[tid];

    // build span_w global image for inv (16*64*64 = 65536 elems over 28672 thr)
    {
        const int gtid = (blockIdx.y * 28 + blockIdx.x) * 256 + tid;
        #pragma unroll
        for (int e = gtid; e < 65536; e += 28672) {
            int g = e >> 12, rem = e & 4095;
            int r = rem >> 6, c = rem & 63;
            float v = (r < 49) ? sw[g * 3136 + r * 64 + c] : 0.f;
            __nv_bfloat16 h = __float2bfloat16(v);
            __nv_bfloat16 l = __float2bfloat16(v - __bfloat162float(h));
            int byte = g * 8192 + r * 128 + ((c * 2) ^ ((r & 7) << 4));
            *(__nv_bfloat16*)((char*)g_sw_img_hi + byte) = h;
            *(__nv_bfloat16*)((char*)g_sw_img_lo + byte) = l;
        }
    }

    // stage x -> bf16 hi/lo [c][px] rows of 240B (dense, coalesced)
    for (int e4 = tid; e4 < 7168; e4 += 256) {
        int c = e4 / 28, p4 = (e4 - c * 28) * 4;
        float4 v = *(const float4*)&x[(size_t)(b * 256 + c) * HW + n0 + p4];
        uint2 H, L;
        split_bf16x4(v, H, L);
        *(uint2*)(smem + R_XBHI + c * 240 + p4 * 2) = H;
        *(uint2*)(smem + R_XBLO + c * 240 + p4 * 2) = L;
    }
    __syncthreads();

    // GEMM: 8 warps = 4 mt x 2 nh; acc[7 n-tiles][4]
    const int wrp = tid >> 5, lane = tid & 31;
    const int mt = wrp >> 1, nh = wrp & 1;
    float acc[7][4];
    #pragma unroll
    for (int j = 0; j < 7; j++)
        #pragma unroll
        for (int q = 0; q < 4; q++) acc[j][q] = 0.f;

    const uint32_t a_off = (uint32_t)((mt * 16 + (lane & 15)) * 128 + ((lane & 16) ? 16 : 0));

    #pragma unroll 1
    for (int kt = 0; kt < 16; kt++) {
        const int q = kt >> 2, ktl = kt & 3;
        uint32_t ahi[4], alo[4];
        ldsm4(ahi, sbase + R_RWHI + q * 8192 + SWZ(a_off + ktl * 32));
        ldsm4(alo, sbase + R_RWLO + q * 8192 + SWZ(a_off + ktl * 32));
        const uint32_t brow = (uint32_t)((kt * 16 + (lane & 15)) * 240);
        #pragma unroll
        for (int j = 0; j < 7; j++) {
            const uint32_t pxo = (uint32_t)(((nh * 7 + j) * 8) * 2);
            uint32_t bh[2], bl[2];
            ldsm2t(bh, sbase + R_XBHI + brow + pxo);
            ldsm2t(bl, sbase + R_XBLO + brow + pxo);
            mma_bf16(acc[j], ahi, bh);
            mma_bf16(acc[j], ahi, bl);
            mma_bf16(acc[j], alo, bh);
        }
    }
    __syncthreads();   // all XB reads done before T overlay

    // transpose through T[112px][68]
    {
        float* T = (float*)(smem + R_T);
        const int gq = lane >> 2, tig = lane & 3;
        const int o = mt * 16 + gq;
        #pragma unroll
        for (int j = 0; j < 7; j++) {
            const int px0 = (nh * 7 + j) * 8 + 2 * tig;
            T[px0 * 68 + o]           = acc[j][0];
            T[(px0 + 1) * 68 + o]     = acc[j][1];
            T[px0 * 68 + o + 8]       = acc[j][2];
            T[(px0 + 1) * 68 + o + 8] = acc[j][3];
        }
    }
    __syncthreads();

    // final: +bias, bf16 hi/lo, pre-swizzled STG
    {
        const float* T = (const float*)(smem + R_T);
        for (int e2 = tid; e2 < 1792; e2 += 256) {
            int px = e2 >> 4, o4 = (e2 & 15) * 4;
            float4 v = *(const float4*)&T[px * 68 + o4];
            v.x += rbs[o4]; v.y += rbs[o4 + 1]; v.z += rbs[o4 + 2]; v.w += rbs[o4 + 3];
            uint2 H, L;
            split_bf16x4(v, H, L);
            size_t rowb = (size_t)(b * HW + n0 + px) * 128;
            int swo = (o4 * 2) ^ (((n0 + px) & 7) << 4);
            *(uint2*)((char*)g_ht_hi + rowb + swo) = H;
            *(uint2*)((char*)g_ht_lo + rowb + swo) = L;
        }
    }
}

// ---------------------------------------------------------------------------
// Kernel 2: HMMA span GEMM + fp32 apply (identical to R12).
// ---------------------------------------------------------------------------
#define SM_WS_HI 0
#define SM_WS_LO 8192
#define SM_H_HI  16384
#define SM_H_LO  45056
#define SM_KERN  16384
#define SM_XT    73728
#define SM_SB    114304
#define SM_TOTAL 114560

__global__ __launch_bounds__(256, 2) void inv_kernel(
    const float* __restrict__ x,
    const float* __restrict__ sw,
    const float* __restrict__ sb,
    float* __restrict__ out)
{
    const int r0 = blockIdx.x * 4;
    const int g  = blockIdx.y;
    const int b  = blockIdx.z;

    extern __shared__ char smem[];
    const int tid = threadIdx.x;
    const uint32_t sbase = smem_u32(smem);
    const int wrp = tid >> 5, lane = tid & 31;

    float* kernsm = (float*)(smem + SM_KERN);
    float* xt     = (float*)(smem + SM_XT);
    float* sbias  = (float*)(smem + SM_SB);

    // ---- ws image copy (pre-swizzled) ----
    {
        uint4* sh = (uint4*)(smem + SM_WS_HI);
        uint4* sl = (uint4*)(smem + SM_WS_LO);
        const uint4* gh = g_sw_img_hi + g * 512;
        const uint4* gl = g_sw_img_lo + g * 512;
        #pragma unroll
        for (int i = 0; i < 2; i++) {
            int e = tid + i * 256;
            sh[e] = gh[e];
            sl[e] = gl[e];
        }
    }
    if (tid < 49) sbias[tid] = sb[g * 49 + tid];

    // ---- h tile copy (pre-swizzled rows) ----
    {
        const uint4* bh = g_ht_hi + (size_t)(b * HW + r0 * 56) * 8;
        const uint4* bl = g_ht_lo + (size_t)(b * HW + r0 * 56) * 8;
        uint4* sh = (uint4*)(smem + SM_H_HI);
        uint4* sl = (uint4*)(smem + SM_H_LO);
        #pragma unroll
        for (int i = 0; i < 7; i++) {
            int e = tid + i * 256;
            sh[e] = bh[e];
            sl[e] = bl[e];
        }
    }

    // ---- x halo tile: job = (ch, row), lanes = cols ----
    {
        #pragma unroll 1
        for (int it = 0; it < 20; it++) {
            int job = it * 8 + wrp;            // 0..159
            int ch = job / 10, rr = job - ch * 10;
            int gr = r0 + rr - 3;
            bool rok = (gr >= 0) && (gr < 56);
            const float* xrow = &x[(size_t)(b * 256 + g * 16 + ch) * HW + gr * 56];
            float* drow = &xt[ch * XCH + rr * 62];
            int c0 = lane, c1 = lane + 32;
            float v0 = 0.f, v1 = 0.f;
            int g0 = c0 - 3, g1 = c1 - 3;
            if (rok && g0 >= 0 && g0 < 56) v0 = xrow[g0];
            if (rok && g1 < 56 && c1 < 62) v1 = xrow[g1];
            drow[c0] = v0;
            if (c1 < 62) drow[c1] = v1;
        }
    }
    __syncthreads();

    // ---- Phase 1: HMMA GEMM kern[64][224] ----
    const int mt = wrp >> 1;
    const int nh = wrp & 1;

    float acc[14][4];
    #pragma unroll
    for (int j = 0; j < 14; j++)
        #pragma unroll
        for (int q = 0; q < 4; q++) acc[j][q] = 0.f;

    const uint32_t a_off = (uint32_t)((mt * 16 + (lane & 15)) * 128 + ((lane & 16) ? 16 : 0));
    const uint32_t b_lane = (uint32_t)((lane & 7) * 128 + ((lane & 8) ? 16 : 0));

    #pragma unroll
    for (int kt = 0; kt < 4; kt++) {
        uint32_t ahi[4], alo[4];
        ldsm4(ahi, sbase + SM_WS_HI + SWZ(a_off + kt * 32));
        ldsm4(alo, sbase + SM_WS_LO + SWZ(a_off + kt * 32));
        #pragma unroll
        for (int j = 0; j < 14; j++) {
            uint32_t boff = SWZ(b_lane + (uint32_t)((nh * 14 + j) * 1024) + kt * 32);
            uint32_t bh[2], bl[2];
            ldsm2(bh, sbase + SM_H_HI + boff);
            ldsm2(bl, sbase + SM_H_LO + boff);
            mma_bf16(acc[j], ahi, bh);
            mma_bf16(acc[j], ahi, bl);
            mma_bf16(acc[j], alo, bh);
        }
    }
    __syncthreads();   // all h reads done before kern overlay writes

    // ---- epilogue: fragments + bias -> kern smem ----
    {
        const int gq = lane >> 2, tig = lane & 3;
        const int kk0 = mt * 16 + gq;
        const int kk1 = kk0 + 8;
        const float b0 = (kk0 < 49) ? sbias[kk0] : 0.f;
        const float b1 = (kk1 < 49) ? sbias[kk1] : 0.f;
        #pragma unroll
        for (int j = 0; j < 14; j++) {
            const int px = (nh * 14 + j) * 8 + 2 * tig;
            if (kk0 < 49) {
                float2 v = {acc[j][0] + b0, acc[j][1] + b0};
                *(float2*)&kernsm[kk0 * KSTR + px] = v;
            }
            if (kk1 < 49) {
                float2 v = {acc[j][2] + b1, acc[j][3] + b1};
                *(float2*)&kernsm[kk1 * KSTR + px] = v;
            }
        }
    }
    __syncthreads();

    // ---- Phase 2: apply. thread = 4 px x 4 interleaved channels ----
    if (tid < 224) {
        const int pd  = tid >> 2;
        const int cq  = tid & 3;
        const int lr  = pd / 14;
        const int pc4 = pd - lr * 14;
        const int pix0 = 4 * pd;
        const int col0 = 4 * pc4;
        const int row  = r0 + lr;

        unsigned long long acc2[4][2];
        #pragma unroll
        for (int i = 0; i < 4; i++)
            #pragma unroll
            for (int j = 0; j < 2; j++) acc2[i][j] = 0ull;

        #pragma unroll 1
        for (int kh = 0; kh < 7; kh++) {
            unsigned long long kc2[7][2];
            #pragma unroll
            for (int kw = 0; kw < 7; kw++)
                #pragma unroll
                for (int j = 0; j < 2; j++) {
                    F2 t; t.f = *(const float2*)&kernsm[(kh * 7 + kw) * KSTR + pix0 + 2 * j];
                    kc2[kw][j] = t.u;
                }

            #pragma unroll
            for (int i = 0; i < 4; i++) {
                const int ch = cq + 4 * i;
                const float* xr = &xt[ch * XCH + (lr + kh) * 62 + col0];
                F2 P[5];
                #pragma unroll
                for (int s = 0; s < 5; s++) P[s].f = *(const float2*)&xr[2 * s];
                unsigned long long M[4];
                #pragma unroll
                for (int s = 0; s < 4; s++) M[s] = pk2f(P[s].f.y, P[s + 1].f.x);

                acc2[i][0] = ffma2(kc2[0][0], P[0].u, acc2[i][0]);
                acc2[i][0] = ffma2(kc2[1][0], M[0],   acc2[i][0]);
                acc2[i][0] = ffma2(kc2[2][0], P[1].u, acc2[i][0]);
                acc2[i][0] = ffma2(kc2[3][0], M[1],   acc2[i][0]);
                acc2[i][0] = ffma2(kc2[4][0], P[2].u, acc2[i][0]);
                acc2[i][0] = ffma2(kc2[5][0], M[2],   acc2[i][0]);
                acc2[i][0] = ffma2(kc2[6][0], P[3].u, acc2[i][0]);

                acc2[i][1] = ffma2(kc2[0][1], P[1].u, acc2[i][1]);
                acc2[i][1] = ffma2(kc2[1][1], M[1],   acc2[i][1]);
                acc2[i][1] = ffma2(kc2[2][1], P[2].u, acc2[i][1]);
                acc2[i][1] = ffma2(kc2[3][1], M[2],   acc2[i][1]);
                acc2[i][1] = ffma2(kc2[4][1], P[3].u, acc2[i][1]);
                acc2[i][1] = ffma2(kc2[5][1], M[3],   acc2[i][1]);
                acc2[i][1] = ffma2(kc2[6][1], P[4].u, acc2[i][1]);
            }
        }

        #pragma unroll
        for (int i = 0; i < 4; i++) {
            const int ch = cq + 4 * i;
            #pragma unroll
            for (int j = 0; j < 2; j++) {
                F2 r; r.u = acc2[i][j];
                *(float2*)&out[(size_t)(b * 256 + g * 16 + ch) * HW + row * 56 + col0 + 2 * j] = r.f;
            }
        }
    }
}

extern "C" void kernel_launch(void* const* d_in, const int* in_sizes, int n_in,
                              void* d_out, int out_size)
{
    const float* x  = (const float*)d_in[0];
    const float* rw = (const float*)d_in[1];
    const float* rb = (const float*)d_in[2];
    const float* sw = (const float*)d_in[3];
    const float* sb = (const float*)d_in[4];
    float* out = (float*)d_out;

    cudaFuncSetAttribute(reduce_mma, cudaFuncAttributeMaxDynamicSharedMemorySize, R_TOTAL);
    cudaFuncSetAttribute(inv_kernel, cudaFuncAttributeMaxDynamicSharedMemorySize, SM_TOTAL);

    reduce_mma<<<dim3(28, 4), 256, R_TOTAL>>>(x, rw, sw, rb);
    inv_kernel<<<dim3(14, 16, 4), 256, SM_TOTAL>>>(x, sw, sb, out);
}

// round 16
// speedup vs baseline: 1.6913x; 1.0739x over previous
#include <cuda_runtime.h>
#include <cuda_bf16.h>
#include <cstdint>

// Involution: B=4, C=256, G=16, K=7, S=1, P=3, H=W=56
#define HW 3136
#define XCH 634    // xt per-channel stride (floats)
#define KSTR 228   // kern row stride (floats)

// h^T[b][px][64o] bf16 hi/lo, rows of 128B stored PRE-SWIZZLED (SW128)
__device__ uint4 g_ht_hi[4 * HW * 8];    // 4*HW rows * 128B
__device__ uint4 g_ht_lo[4 * HW * 8];
// span_w image: bf16 hi/lo, SW128 pre-swizzled rows of 128B (built by reduce_mma)
__device__ uint4 g_sw_img_hi[8192];      // [16 g][64 row][64 c] = 128KB
__device__ uint4 g_sw_img_lo[8192];

// ---- f32x2 helpers ----
union F2 { float2 f; unsigned long long u; };
union F4 { float4 f; unsigned long long u[2]; };
__device__ __forceinline__ unsigned long long pk2f(float lo, float hi) {
    unsigned long long d;
    asm("mov.b64 %0, {%1, %2};" : "=l"(d) : "f"(lo), "f"(hi));
    return d;
}
__device__ __forceinline__ unsigned long long ffma2(
    unsigned long long a, unsigned long long b, unsigned long long c) {
    unsigned long long d;
    asm("fma.rn.f32x2 %0, %1, %2, %3;" : "=l"(d) : "l"(a), "l"(b), "l"(c));
    return d;
}

// ---- mma / ldmatrix / cp.async helpers ----
__device__ __forceinline__ uint32_t smem_u32(const void* p) {
    uint32_t a;
    asm("{ .reg .u64 t; cvta.to.shared.u64 t, %1; cvt.u32.u64 %0, t; }" : "=r"(a) : "l"(p));
    return a;
}
#define SWZ(o) ((o) ^ (((o) >> 3) & 0x70))
__device__ __forceinline__ void ldsm4(uint32_t* r, uint32_t addr) {
    asm volatile("ldmatrix.sync.aligned.m8n8.x4.shared.b16 {%0,%1,%2,%3}, [%4];"
        : "=r"(r[0]), "=r"(r[1]), "=r"(r[2]), "=r"(r[3]) : "r"(addr));
}
__device__ __forceinline__ void ldsm2(uint32_t* r, uint32_t addr) {
    asm volatile("ldmatrix.sync.aligned.m8n8.x2.shared.b16 {%0,%1}, [%2];"
        : "=r"(r[0]), "=r"(r[1]) : "r"(addr));
}
__device__ __forceinline__ void ldsm2t(uint32_t* r, uint32_t addr) {
    asm volatile("ldmatrix.sync.aligned.m8n8.x2.trans.shared.b16 {%0,%1}, [%2];"
        : "=r"(r[0]), "=r"(r[1]) : "r"(addr));
}
__device__ __forceinline__ void mma_bf16(float* c, const uint32_t* a, const uint32_t* b) {
    asm volatile("mma.sync.aligned.m16n8k16.row.col.f32.bf16.bf16.f32 "
        "{%0,%1,%2,%3}, {%4,%5,%6,%7}, {%8,%9}, {%0,%1,%2,%3};"
        : "+f"(c[0]), "+f"(c[1]), "+f"(c[2]), "+f"(c[3])
        : "r"(a[0]), "r"(a[1]), "r"(a[2]), "r"(a[3]), "r"(b[0]), "r"(b[1]));
}
__device__ __forceinline__ void cp_async4(uint32_t dst, const void* src, bool pred) {
    int sz = pred ? 4 : 0;
    asm volatile("cp.async.ca.shared.global [%0], [%1], 4, %2;"
                 :: "r"(dst), "l"(src), "r"(sz) : "memory");
}

__device__ __forceinline__ void split_bf16x4(const float4& v, uint2& H, uint2& L) {
    __nv_bfloat162 h0 = __floats2bfloat162_rn(v.x, v.y);
    __nv_bfloat162 h1 = __floats2bfloat162_rn(v.z, v.w);
    __nv_bfloat162 l0 = __floats2bfloat162_rn(v.x - __bfloat162float(h0.x),
                                              v.y - __bfloat162float(h0.y));
    __nv_bfloat162 l1 = __floats2bfloat162_rn(v.z - __bfloat162float(h1.x),
                                              v.w - __bfloat162float(h1.y));
    union { __nv_bfloat162 b2[2]; uint2 u; } t;
    t.b2[0] = h0; t.b2[1] = h1; H = t.u;
    t.b2[0] = l0; t.b2[1] = l1; L = t.u;
}

// ---------------------------------------------------------------------------
// Kernel 1 (HMMA): h^T[b][px][o] = rw @ x, grid (28,4), 256 thr.
// Converts rw inline into smem and builds the span_w global image for inv.
// ---------------------------------------------------------------------------
#define R_RWHI 0
#define R_RWLO 32768
#define R_XBHI 65536               // 256 rows x 240B = 61440
#define R_XBLO 126976
#define R_T    65536               // overlay: 112*68*4 = 30464
#define R_RB   188416              // 64 floats
#define R_TOTAL 188672

__global__ __launch_bounds__(256) void reduce_mma(
    const float* __restrict__ x,
    const float* __restrict__ rw,
    const float* __restrict__ sw,
    const float* __restrict__ rb)
{
    const int b  = blockIdx.y;
    const int n0 = blockIdx.x * 112;
    extern __shared__ char smem[];
    const int tid = threadIdx.x;
    const uint32_t sbase = smem_u32(smem);
    float* rbs = (float*)(smem + R_RB);

    // rw -> smem bf16 hi/lo, SW128 swizzled (inline conversion, coalesced)
    #pragma unroll
    for (int i = 0; i < 16; i++) {
        int e4 = tid + i * 256;
        int o = e4 >> 6;
        int c = (e4 & 63) * 4;
        int chunk = c >> 6, cl = c & 63;
        float4 v = *(const float4*)&rw[e4 * 4];
        uint2 H, L;
        split_bf16x4(v, H, L);
        int byte = chunk * 8192 + o * 128 + ((cl * 2) ^ ((o & 7) << 4));
        *(uint2*)(smem + R_RWHI + byte) = H;
        *(uint2*)(smem + R_RWLO + byte) = L;
    }
    if (tid < 64) rbs[tid] = rb[tid];

    // build span_w global image for inv
    {
        const int gtid = (blockIdx.y * 28 + blockIdx.x) * 256 + tid;
        #pragma unroll
        for (int e = gtid; e < 65536; e += 28672) {
            int g = e >> 12, rem = e & 4095;
            int r = rem >> 6, c = rem & 63;
            float v = (r < 49) ? sw[g * 3136 + r * 64 + c] : 0.f;
            __nv_bfloat16 h = __float2bfloat16(v);
            __nv_bfloat16 l = __float2bfloat16(v - __bfloat162float(h));
            int byte = g * 8192 + r * 128 + ((c * 2) ^ ((r & 7) << 4));
            *(__nv_bfloat16*)((char*)g_sw_img_hi + byte) = h;
            *(__nv_bfloat16*)((char*)g_sw_img_lo + byte) = l;
        }
    }

    // stage x -> bf16 hi/lo [c][px] rows of 240B
    for (int e4 = tid; e4 < 7168; e4 += 256) {
        int c = e4 / 28, p4 = (e4 - c * 28) * 4;
        float4 v = *(const float4*)&x[(size_t)(b * 256 + c) * HW + n0 + p4];
        uint2 H, L;
        split_bf16x4(v, H, L);
        *(uint2*)(smem + R_XBHI + c * 240 + p4 * 2) = H;
        *(uint2*)(smem + R_XBLO + c * 240 + p4 * 2) = L;
    }
    __syncthreads();

    // GEMM: 8 warps = 4 mt x 2 nh; acc[7 n-tiles][4]
    const int wrp = tid >> 5, lane = tid & 31;
    const int mt = wrp >> 1, nh = wrp & 1;
    float acc[7][4];
    #pragma unroll
    for (int j = 0; j < 7; j++)
        #pragma unroll
        for (int q = 0; q < 4; q++) acc[j][q] = 0.f;

    const uint32_t a_off = (uint32_t)((mt * 16 + (lane & 15)) * 128 + ((lane & 16) ? 16 : 0));

    #pragma unroll 1
    for (int kt = 0; kt < 16; kt++) {
        const int q = kt >> 2, ktl = kt & 3;
        uint32_t ahi[4], alo[4];
        ldsm4(ahi, sbase + R_RWHI + q * 8192 + SWZ(a_off + ktl * 32));
        ldsm4(alo, sbase + R_RWLO + q * 8192 + SWZ(a_off + ktl * 32));
        const uint32_t brow = (uint32_t)((kt * 16 + (lane & 15)) * 240);
        #pragma unroll
        for (int j = 0; j < 7; j++) {
            const uint32_t pxo = (uint32_t)(((nh * 7 + j) * 8) * 2);
            uint32_t bh[2], bl[2];
            ldsm2t(bh, sbase + R_XBHI + brow + pxo);
            ldsm2t(bl, sbase + R_XBLO + brow + pxo);
            mma_bf16(acc[j], ahi, bh);
            mma_bf16(acc[j], ahi, bl);
            mma_bf16(acc[j], alo, bh);
        }
    }
    __syncthreads();

    // transpose through T[112px][68]
    {
        float* T = (float*)(smem + R_T);
        const int gq = lane >> 2, tig = lane & 3;
        const int o = mt * 16 + gq;
        #pragma unroll
        for (int j = 0; j < 7; j++) {
            const int px0 = (nh * 7 + j) * 8 + 2 * tig;
            T[px0 * 68 + o]           = acc[j][0];
            T[(px0 + 1) * 68 + o]     = acc[j][1];
            T[px0 * 68 + o + 8]       = acc[j][2];
            T[(px0 + 1) * 68 + o + 8] = acc[j][3];
        }
    }
    __syncthreads();

    // final: +bias, bf16 hi/lo, pre-swizzled STG
    {
        const float* T = (const float*)(smem + R_T);
        for (int e2 = tid; e2 < 1792; e2 += 256) {
            int px = e2 >> 4, o4 = (e2 & 15) * 4;
            float4 v = *(const float4*)&T[px * 68 + o4];
            v.x += rbs[o4]; v.y += rbs[o4 + 1]; v.z += rbs[o4 + 2]; v.w += rbs[o4 + 3];
            uint2 H, L;
            split_bf16x4(v, H, L);
            size_t rowb = (size_t)(b * HW + n0 + px) * 128;
            int swo = (o4 * 2) ^ (((n0 + px) & 7) << 4);
            *(uint2*)((char*)g_ht_hi + rowb + swo) = H;
            *(uint2*)((char*)g_ht_lo + rowb + swo) = L;
        }
    }
}

// ---------------------------------------------------------------------------
// Kernel 2: HMMA span GEMM + fp32 apply.
// xt halo staged via cp.async (zero-fill), overlapped with phase-1 GEMM.
// ---------------------------------------------------------------------------
#define SM_WS_HI 0
#define SM_WS_LO 8192
#define SM_H_HI  16384
#define SM_H_LO  45056
#define SM_KERN  16384
#define SM_XT    73728
#define SM_SB    114304
#define SM_TOTAL 114560

__global__ __launch_bounds__(256, 2) void inv_kernel(
    const float* __restrict__ x,
    const float* __restrict__ sw,
    const float* __restrict__ sb,
    float* __restrict__ out)
{
    const int r0 = blockIdx.x * 4;
    const int g  = blockIdx.y;
    const int b  = blockIdx.z;

    extern __shared__ char smem[];
    const int tid = threadIdx.x;
    const uint32_t sbase = smem_u32(smem);
    const int wrp = tid >> 5, lane = tid & 31;

    float* kernsm = (float*)(smem + SM_KERN);
    float* xt     = (float*)(smem + SM_XT);
    float* sbias  = (float*)(smem + SM_SB);

    // ---- issue xt halo cp.asyncs FIRST (consumed only in phase 2) ----
    {
        const float* xg = &x[(size_t)(b * 256 + g * 16) * HW];
        #pragma unroll 1
        for (int it = 0; it < 20; it++) {
            int job = it * 8 + wrp;            // (ch, halo-row), 0..159
            int ch = job / 10, rr = job - ch * 10;
            int gr = r0 + rr - 3;
            bool rok = (gr >= 0) && (gr < 56);
            const float* xrow = xg + (size_t)ch * HW + (rok ? gr * 56 : 0);
            uint32_t drow = sbase + SM_XT + 4 * (ch * XCH + rr * 62);
            int c0 = lane, c1 = lane + 32;
            int g0 = c0 - 3, g1 = c1 - 3;
            bool ok0 = rok && (g0 >= 0) && (g0 < 56);
            bool ok1 = rok && (g1 < 56);
            cp_async4(drow + 4 * c0, xrow + (ok0 ? g0 : 0), ok0);
            if (c1 < 62)
                cp_async4(drow + 4 * c1, xrow + (ok1 ? g1 : 0), ok1);
        }
        asm volatile("cp.async.commit_group;" ::: "memory");
    }

    // ---- ws image copy (pre-swizzled) ----
    {
        uint4* sh = (uint4*)(smem + SM_WS_HI);
        uint4* sl = (uint4*)(smem + SM_WS_LO);
        const uint4* gh = g_sw_img_hi + g * 512;
        const uint4* gl = g_sw_img_lo + g * 512;
        #pragma unroll
        for (int i = 0; i < 2; i++) {
            int e = tid + i * 256;
            sh[e] = gh[e];
            sl[e] = gl[e];
        }
    }
    if (tid < 49) sbias[tid] = sb[g * 49 + tid];

    // ---- h tile copy (pre-swizzled rows) ----
    {
        const uint4* bh = g_ht_hi + (size_t)(b * HW + r0 * 56) * 8;
        const uint4* bl = g_ht_lo + (size_t)(b * HW + r0 * 56) * 8;
        uint4* sh = (uint4*)(smem + SM_H_HI);
        uint4* sl = (uint4*)(smem + SM_H_LO);
        #pragma unroll
        for (int i = 0; i < 7; i++) {
            int e = tid + i * 256;
            sh[e] = bh[e];
            sl[e] = bl[e];
        }
    }
    __syncthreads();   // ws + h visible (xt still in flight)

    // ---- Phase 1: HMMA GEMM kern[64][224] ----
    const int mt = wrp >> 1;
    const int nh = wrp & 1;

    float acc[14][4];
    #pragma unroll
    for (int j = 0; j < 14; j++)
        #pragma unroll
        for (int q = 0; q < 4; q++) acc[j][q] = 0.f;

    const uint32_t a_off = (uint32_t)((mt * 16 + (lane & 15)) * 128 + ((lane & 16) ? 16 : 0));
    const uint32_t b_lane = (uint32_t)((lane & 7) * 128 + ((lane & 8) ? 16 : 0));

    #pragma unroll
    for (int kt = 0; kt < 4; kt++) {
        uint32_t ahi[4], alo[4];
        ldsm4(ahi, sbase + SM_WS_HI + SWZ(a_off + kt * 32));
        ldsm4(alo, sbase + SM_WS_LO + SWZ(a_off + kt * 32));
        #pragma unroll
        for (int j = 0; j < 14; j++) {
            uint32_t boff = SWZ(b_lane + (uint32_t)((nh * 14 + j) * 1024) + kt * 32);
            uint32_t bh[2], bl[2];
            ldsm2(bh, sbase + SM_H_HI + boff);
            ldsm2(bl, sbase + SM_H_LO + boff);
            mma_bf16(acc[j], ahi, bh);
            mma_bf16(acc[j], ahi, bl);
            mma_bf16(acc[j], alo, bh);
        }
    }
    __syncthreads();   // all h reads done before kern overlay writes

    // ---- epilogue: fragments + bias -> kern smem ----
    {
        const int gq = lane >> 2, tig = lane & 3;
        const int kk0 = mt * 16 + gq;
        const int kk1 = kk0 + 8;
        const float b0 = (kk0 < 49) ? sbias[kk0] : 0.f;
        const float b1 = (kk1 < 49) ? sbias[kk1] : 0.f;
        #pragma unroll
        for (int j = 0; j < 14; j++) {
            const int px = (nh * 14 + j) * 8 + 2 * tig;
            if (kk0 < 49) {
                float2 v = {acc[j][0] + b0, acc[j][1] + b0};
                *(float2*)&kernsm[kk0 * KSTR + px] = v;
            }
            if (kk1 < 49) {
                float2 v = {acc[j][2] + b1, acc[j][3] + b1};
                *(float2*)&kernsm[kk1 * KSTR + px] = v;
            }
        }
    }
    asm volatile("cp.async.wait_group 0;" ::: "memory");   // xt landed
    __syncthreads();

    // ---- Phase 2: apply. thread = 4 px x 4 interleaved channels ----
    if (tid < 224) {
        const int pd  = tid >> 2;
        const int cq  = tid & 3;
        const int lr  = pd / 14;
        const int pc4 = pd - lr * 14;
        const int pix0 = 4 * pd;
        const int col0 = 4 * pc4;
        const int row  = r0 + lr;

        unsigned long long acc2[4][2];
        #pragma unroll
        for (int i = 0; i < 4; i++)
            #pragma unroll
            for (int j = 0; j < 2; j++) acc2[i][j] = 0ull;

        #pragma unroll 1
        for (int kh = 0; kh < 7; kh++) {
            unsigned long long kc2[7][2];
            #pragma unroll
            for (int kw = 0; kw < 7; kw++) {
                F4 t;
                t.f = *(const float4*)&kernsm[(kh * 7 + kw) * KSTR + pix0];
                kc2[kw][0] = t.u[0];
                kc2[kw][1] = t.u[1];
            }

            #pragma unroll
            for (int i = 0; i < 4; i++) {
                const int ch = cq + 4 * i;
                const float* xr = &xt[ch * XCH + (lr + kh) * 62 + col0];
                F2 P[5];
                #pragma unroll
                for (int s = 0; s < 5; s++) P[s].f = *(const float2*)&xr[2 * s];
                unsigned long long M[4];
                #pragma unroll
                for (int s = 0; s < 4; s++) M[s] = pk2f(P[s].f.y, P[s + 1].f.x);

                acc2[i][0] = ffma2(kc2[0][0], P[0].u, acc2[i][0]);
                acc2[i][0] = ffma2(kc2[1][0], M[0],   acc2[i][0]);
                acc2[i][0] = ffma2(kc2[2][0], P[1].u, acc2[i][0]);
                acc2[i][0] = ffma2(kc2[3][0], M[1],   acc2[i][0]);
                acc2[i][0] = ffma2(kc2[4][0], P[2].u, acc2[i][0]);
                acc2[i][0] = ffma2(kc2[5][0], M[2],   acc2[i][0]);
                acc2[i][0] = ffma2(kc2[6][0], P[3].u, acc2[i][0]);

                acc2[i][1] = ffma2(kc2[0][1], P[1].u, acc2[i][1]);
                acc2[i][1] = ffma2(kc2[1][1], M[1],   acc2[i][1]);
                acc2[i][1] = ffma2(kc2[2][1], P[2].u, acc2[i][1]);
                acc2[i][1] = ffma2(kc2[3][1], M[2],   acc2[i][1]);
                acc2[i][1] = ffma2(kc2[4][1], P[3].u, acc2[i][1]);
                acc2[i][1] = ffma2(kc2[5][1], M[3],   acc2[i][1]);
                acc2[i][1] = ffma2(kc2[6][1], P[4].u, acc2[i][1]);
            }
        }

        #pragma unroll
        for (int i = 0; i < 4; i++) {
            const int ch = cq + 4 * i;
            #pragma unroll
            for (int j = 0; j < 2; j++) {
                F2 r; r.u = acc2[i][j];
                *(float2*)&out[(size_t)(b * 256 + g * 16 + ch) * HW + row * 56 + col0 + 2 * j] = r.f;
            }
        }
    }
}

extern "C" void kernel_launch(void* const* d_in, const int* in_sizes, int n_in,
                              void* d_out, int out_size)
{
    const float* x  = (const float*)d_in[0];
    const float* rw = (const float*)d_in[1];
    const float* rb = (const float*)d_in[2];
    const float* sw = (const float*)d_in[3];
    const float* sb = (const float*)d_in[4];
    float* out = (float*)d_out;

    cudaFuncSetAttribute(reduce_mma, cudaFuncAttributeMaxDynamicSharedMemorySize, R_TOTAL);
    cudaFuncSetAttribute(inv_kernel, cudaFuncAttributeMaxDynamicSharedMemorySize, SM_TOTAL);

    reduce_mma<<<dim3(28, 4), 256, R_TOTAL>>>(x, rw, sw, rb);
    inv_kernel<<<dim3(14, 16, 4), 256, SM_TOTAL>>>(x, sw, sb, out);
}